// round 1
// baseline (speedup 1.0000x reference)
#include <cuda_runtime.h>

// 3-level fused Haar DWT (DWTForward, J=3, zero-pad mode).
// x: (8,32,512,512) fp32. Output tuple flattened:
//   ll   (8,32,64,64)      @ 0
//   yh0  (8,32,3,256,256)  @ 1048576
//   yh1  (8,32,3,128,128)  @ 51380224
//   yh2  (8,32,3,64,64)    @ 63963136
// With L=2 filters and even sizes, pad p=0 at every level: each level is a
// non-overlapping 2x2 block transform, so one thread processes one 8x8 input
// tile through all 3 levels entirely in registers.

#define OFF_YH0 1048576UL
#define OFF_YH1 51380224UL
#define OFF_YH2 63963136UL

__global__ __launch_bounds__(256) void dwt3_fused_kernel(
    const float* __restrict__ x,
    const float* __restrict__ h0c, const float* __restrict__ h1c,
    const float* __restrict__ h0r, const float* __restrict__ h1r,
    float* __restrict__ out)
{
    const int gid = blockIdx.x * 256 + threadIdx.x;
    const int bx  = gid & 63;          // tile column (0..63) -> coalesced writes
    const int by  = (gid >> 6) & 63;   // tile row
    const int img = gid >> 12;         // n*32 + c  (0..255)

    // filter taps (broadcast loads, L1-resident after first warp)
    const float f0r0 = h0r[0], f0r1 = h0r[1];
    const float f1r0 = h1r[0], f1r1 = h1r[1];
    const float f0c0 = h0c[0], f0c1 = h0c[1];
    const float f1c0 = h1c[0], f1c1 = h1c[1];

    const float* xp = x + (size_t)img * (512u * 512u)
                        + (size_t)(by * 8) * 512u + (size_t)bx * 8u;

    float* yh0 = out + OFF_YH0 + (size_t)img * (3u * 256u * 256u);
    float* yh1 = out + OFF_YH1 + (size_t)img * (3u * 128u * 128u);
    float* yh2 = out + OFF_YH2 + (size_t)img * (3u * 64u * 64u);
    float* llp = out            + (size_t)img * (64u * 64u);

    // ---------------- level 1: 8x8 -> 4x4 per subband ----------------
    float ll1[4][4];
    #pragma unroll
    for (int r = 0; r < 4; r++) {
        const float4* rowt = (const float4*)(xp + (size_t)(2 * r)     * 512u);
        const float4* rowb = (const float4*)(xp + (size_t)(2 * r + 1) * 512u);
        float4 t0 = rowt[0], t1 = rowt[1];
        float4 u0 = rowb[0], u1 = rowb[1];
        float at[8] = {t0.x, t0.y, t0.z, t0.w, t1.x, t1.y, t1.z, t1.w};
        float ab[8] = {u0.x, u0.y, u0.z, u0.w, u1.x, u1.y, u1.z, u1.w};
        float lh[4], hl[4], hh[4];
        #pragma unroll
        for (int j = 0; j < 4; j++) {
            float A = at[2*j], B = at[2*j+1];
            float C = ab[2*j], D = ab[2*j+1];
            float rlo_t = f0r0 * A + f0r1 * B;   // row lowpass, top row
            float rhi_t = f1r0 * A + f1r1 * B;   // row highpass, top row
            float rlo_b = f0r0 * C + f0r1 * D;
            float rhi_b = f1r0 * C + f1r1 * D;
            ll1[r][j] = f0c0 * rlo_t + f0c1 * rlo_b;
            lh[j]     = f1c0 * rlo_t + f1c1 * rlo_b;  // row-lo, col-hi
            hl[j]     = f0c0 * rhi_t + f0c1 * rhi_b;  // row-hi, col-lo
            hh[j]     = f1c0 * rhi_t + f1c1 * rhi_b;
        }
        size_t row_off = (size_t)(by * 4 + r) * 256u + (size_t)bx * 4u;
        *(float4*)(yh0 + 0u * 65536u + row_off) = make_float4(lh[0], lh[1], lh[2], lh[3]);
        *(float4*)(yh0 + 1u * 65536u + row_off) = make_float4(hl[0], hl[1], hl[2], hl[3]);
        *(float4*)(yh0 + 2u * 65536u + row_off) = make_float4(hh[0], hh[1], hh[2], hh[3]);
    }

    // ---------------- level 2: 4x4 ll1 -> 2x2 per subband ----------------
    float ll2[2][2];
    #pragma unroll
    for (int r = 0; r < 2; r++) {
        float lh[2], hl[2], hh[2];
        #pragma unroll
        for (int j = 0; j < 2; j++) {
            float A = ll1[2*r][2*j],   B = ll1[2*r][2*j+1];
            float C = ll1[2*r+1][2*j], D = ll1[2*r+1][2*j+1];
            float rlo_t = f0r0 * A + f0r1 * B;
            float rhi_t = f1r0 * A + f1r1 * B;
            float rlo_b = f0r0 * C + f0r1 * D;
            float rhi_b = f1r0 * C + f1r1 * D;
            ll2[r][j] = f0c0 * rlo_t + f0c1 * rlo_b;
            lh[j]     = f1c0 * rlo_t + f1c1 * rlo_b;
            hl[j]     = f0c0 * rhi_t + f0c1 * rhi_b;
            hh[j]     = f1c0 * rhi_t + f1c1 * rhi_b;
        }
        size_t row_off = (size_t)(by * 2 + r) * 128u + (size_t)bx * 2u;
        *(float2*)(yh1 + 0u * 16384u + row_off) = make_float2(lh[0], lh[1]);
        *(float2*)(yh1 + 1u * 16384u + row_off) = make_float2(hl[0], hl[1]);
        *(float2*)(yh1 + 2u * 16384u + row_off) = make_float2(hh[0], hh[1]);
    }

    // ---------------- level 3: 2x2 ll2 -> 1x1 per subband ----------------
    {
        float A = ll2[0][0], B = ll2[0][1];
        float C = ll2[1][0], D = ll2[1][1];
        float rlo_t = f0r0 * A + f0r1 * B;
        float rhi_t = f1r0 * A + f1r1 * B;
        float rlo_b = f0r0 * C + f0r1 * D;
        float rhi_b = f1r0 * C + f1r1 * D;
        size_t off = (size_t)by * 64u + (size_t)bx;
        llp[off]              = f0c0 * rlo_t + f0c1 * rlo_b;
        yh2[0u * 4096u + off] = f1c0 * rlo_t + f1c1 * rlo_b;
        yh2[1u * 4096u + off] = f0c0 * rhi_t + f0c1 * rhi_b;
        yh2[2u * 4096u + off] = f1c0 * rhi_t + f1c1 * rhi_b;
    }
}

extern "C" void kernel_launch(void* const* d_in, const int* in_sizes, int n_in,
                              void* d_out, int out_size)
{
    const float* x   = (const float*)d_in[0];
    const float* h0c = (const float*)d_in[1];
    const float* h1c = (const float*)d_in[2];
    const float* h0r = (const float*)d_in[3];
    const float* h1r = (const float*)d_in[4];
    float* out = (float*)d_out;

    // 8*32 images, 64*64 tiles each -> 1,048,576 threads
    dwt3_fused_kernel<<<4096, 256>>>(x, h0c, h1c, h0r, h1r, out);
}

// round 2
// speedup vs baseline: 1.0183x; 1.0183x over previous
#include <cuda_runtime.h>

// 3-level fused Haar DWT (DWTForward, J=3, zero-pad mode).
// x: (8,32,512,512) fp32. Output tuple flattened:
//   ll   (8,32,64,64)      @ 0
//   yh0  (8,32,3,256,256)  @ 1048576
//   yh1  (8,32,3,128,128)  @ 51380224
//   yh2  (8,32,3,64,64)    @ 63963136
// p=0 at every level (L=2, even sizes): each level is a non-overlapping 2x2
// block transform -> one thread = one 8x8 input tile, all 3 levels in regs.
//
// R2 changes vs R1: (a) streaming cache hints (__ldcs/__stcs) — zero reuse,
// don't allocate in L2; (b) front-load the entire 8x8 tile (16x float4) to
// maximize per-warp MLP before any compute.

#define OFF_YH0 1048576UL
#define OFF_YH1 51380224UL
#define OFF_YH2 63963136UL

__device__ __forceinline__ float4 ldcs4(const float* p) {
    return __ldcs((const float4*)p);
}
__device__ __forceinline__ void stcs4(float* p, float4 v) {
    __stcs((float4*)p, v);
}
__device__ __forceinline__ void stcs2(float* p, float2 v) {
    __stcs((float2*)p, v);
}

__global__ __launch_bounds__(256) void dwt3_fused_kernel(
    const float* __restrict__ x,
    const float* __restrict__ h0c, const float* __restrict__ h1c,
    const float* __restrict__ h0r, const float* __restrict__ h1r,
    float* __restrict__ out)
{
    const int gid = blockIdx.x * 256 + threadIdx.x;
    const int bx  = gid & 63;          // tile column (0..63) -> coalesced
    const int by  = (gid >> 6) & 63;   // tile row
    const int img = gid >> 12;         // n*32 + c  (0..255)

    const float* xp = x + (size_t)img * (512u * 512u)
                        + (size_t)(by * 8) * 512u + (size_t)bx * 8u;

    // ---- front-load the full 8x8 tile: 16 float4 loads in flight ----
    float4 v[8][2];
    #pragma unroll
    for (int r = 0; r < 8; r++) {
        v[r][0] = ldcs4(xp + (size_t)r * 512u);
        v[r][1] = ldcs4(xp + (size_t)r * 512u + 4u);
    }

    // filter taps (broadcast loads)
    const float f0r0 = h0r[0], f0r1 = h0r[1];
    const float f1r0 = h1r[0], f1r1 = h1r[1];
    const float f0c0 = h0c[0], f0c1 = h0c[1];
    const float f1c0 = h1c[0], f1c1 = h1c[1];

    float* yh0 = out + OFF_YH0 + (size_t)img * (3u * 256u * 256u);
    float* yh1 = out + OFF_YH1 + (size_t)img * (3u * 128u * 128u);
    float* yh2 = out + OFF_YH2 + (size_t)img * (3u * 64u * 64u);
    float* llp = out            + (size_t)img * (64u * 64u);

    // ---------------- level 1: 8x8 -> 4x4 per subband ----------------
    float ll1[4][4];
    #pragma unroll
    for (int r = 0; r < 4; r++) {
        float at[8] = {v[2*r][0].x,   v[2*r][0].y,   v[2*r][0].z,   v[2*r][0].w,
                       v[2*r][1].x,   v[2*r][1].y,   v[2*r][1].z,   v[2*r][1].w};
        float ab[8] = {v[2*r+1][0].x, v[2*r+1][0].y, v[2*r+1][0].z, v[2*r+1][0].w,
                       v[2*r+1][1].x, v[2*r+1][1].y, v[2*r+1][1].z, v[2*r+1][1].w};
        float lh[4], hl[4], hh[4];
        #pragma unroll
        for (int j = 0; j < 4; j++) {
            float A = at[2*j], B = at[2*j+1];
            float C = ab[2*j], D = ab[2*j+1];
            float rlo_t = f0r0 * A + f0r1 * B;
            float rhi_t = f1r0 * A + f1r1 * B;
            float rlo_b = f0r0 * C + f0r1 * D;
            float rhi_b = f1r0 * C + f1r1 * D;
            ll1[r][j] = f0c0 * rlo_t + f0c1 * rlo_b;
            lh[j]     = f1c0 * rlo_t + f1c1 * rlo_b;
            hl[j]     = f0c0 * rhi_t + f0c1 * rhi_b;
            hh[j]     = f1c0 * rhi_t + f1c1 * rhi_b;
        }
        size_t row_off = (size_t)(by * 4 + r) * 256u + (size_t)bx * 4u;
        stcs4(yh0 + 0u * 65536u + row_off, make_float4(lh[0], lh[1], lh[2], lh[3]));
        stcs4(yh0 + 1u * 65536u + row_off, make_float4(hl[0], hl[1], hl[2], hl[3]));
        stcs4(yh0 + 2u * 65536u + row_off, make_float4(hh[0], hh[1], hh[2], hh[3]));
    }

    // ---------------- level 2: 4x4 ll1 -> 2x2 per subband ----------------
    float ll2[2][2];
    #pragma unroll
    for (int r = 0; r < 2; r++) {
        float lh[2], hl[2], hh[2];
        #pragma unroll
        for (int j = 0; j < 2; j++) {
            float A = ll1[2*r][2*j],   B = ll1[2*r][2*j+1];
            float C = ll1[2*r+1][2*j], D = ll1[2*r+1][2*j+1];
            float rlo_t = f0r0 * A + f0r1 * B;
            float rhi_t = f1r0 * A + f1r1 * B;
            float rlo_b = f0r0 * C + f0r1 * D;
            float rhi_b = f1r0 * C + f1r1 * D;
            ll2[r][j] = f0c0 * rlo_t + f0c1 * rlo_b;
            lh[j]     = f1c0 * rlo_t + f1c1 * rlo_b;
            hl[j]     = f0c0 * rhi_t + f0c1 * rhi_b;
            hh[j]     = f1c0 * rhi_t + f1c1 * rhi_b;
        }
        size_t row_off = (size_t)(by * 2 + r) * 128u + (size_t)bx * 2u;
        stcs2(yh1 + 0u * 16384u + row_off, make_float2(lh[0], lh[1]));
        stcs2(yh1 + 1u * 16384u + row_off, make_float2(hl[0], hl[1]));
        stcs2(yh1 + 2u * 16384u + row_off, make_float2(hh[0], hh[1]));
    }

    // ---------------- level 3: 2x2 ll2 -> 1x1 per subband ----------------
    {
        float A = ll2[0][0], B = ll2[0][1];
        float C = ll2[1][0], D = ll2[1][1];
        float rlo_t = f0r0 * A + f0r1 * B;
        float rhi_t = f1r0 * A + f1r1 * B;
        float rlo_b = f0r0 * C + f0r1 * D;
        float rhi_b = f1r0 * C + f1r1 * D;
        size_t off = (size_t)by * 64u + (size_t)bx;
        __stcs(llp + off,              f0c0 * rlo_t + f0c1 * rlo_b);
        __stcs(yh2 + 0u * 4096u + off, f1c0 * rlo_t + f1c1 * rlo_b);
        __stcs(yh2 + 1u * 4096u + off, f0c0 * rhi_t + f0c1 * rhi_b);
        __stcs(yh2 + 2u * 4096u + off, f1c0 * rhi_t + f1c1 * rhi_b);
    }
}

extern "C" void kernel_launch(void* const* d_in, const int* in_sizes, int n_in,
                              void* d_out, int out_size)
{
    const float* x   = (const float*)d_in[0];
    const float* h0c = (const float*)d_in[1];
    const float* h1c = (const float*)d_in[2];
    const float* h0r = (const float*)d_in[3];
    const float* h1r = (const float*)d_in[4];
    float* out = (float*)d_out;

    dwt3_fused_kernel<<<4096, 256>>>(x, h0c, h1c, h0r, h1r, out);
}